// round 1
// baseline (speedup 1.0000x reference)
#include <cuda_runtime.h>
#include <math.h>

#define BB 32
#define SC 128
#define NM 16
#define DM 512
#define HH 8
#define DH 64
#define NC 39998
#define MQ (BB*NM)   /* 512 gathered query rows */

// ---------------- scratch (device globals; no allocation allowed) -------------
__device__ float g_curr[BB*SC*DM];   // embedded curr + positional encoding
__device__ float g_K[BB*SC*DM];
__device__ float g_V[BB*SC*DM];
__device__ float g_Qin[MQ*DM];       // gathered embedding rows for Q
__device__ float g_Q[MQ*DM];
__device__ float g_attn[MQ*DM];
__device__ float g_tanh[MQ*DM];
__device__ float g_hyb[MQ*DM];

// ---------------- kernel 1: gather + positional embedding --------------------
__global__ void gather_pe_kernel(const int* __restrict__ idx,
                                 const float* __restrict__ emb,
                                 float* __restrict__ out) {
    int i = blockIdx.x * blockDim.x + threadIdx.x;
    if (i >= BB * SC * DM) return;
    int d   = i & (DM - 1);
    int row = i / DM;
    int s   = row & (SC - 1);
    int g   = idx[row];
    int i2  = d & ~1;
    // div_term = exp(-(2j) * ln(10000)/512)
    float freq = expf((float)i2 * -0.0179889460176f);
    float ang  = (float)s * freq;
    float pe   = (d & 1) ? cosf(ang) : sinf(ang);
    out[i] = emb[(size_t)g * DM + d] + pe;
}

// ---------------- kernel 2: gather Q input rows at mask positions ------------
__global__ void gather_q_kernel(const int* __restrict__ mask_pos,
                                const float* __restrict__ curr,
                                float* __restrict__ out) {
    int i = blockIdx.x * blockDim.x + threadIdx.x;
    if (i >= MQ * DM) return;
    int d = i & (DM - 1);
    int r = i / DM;             // b*NM + m
    int b = r / NM;
    int p = mask_pos[r];        // in [0,128)
    out[i] = curr[((size_t)b * SC + p) * DM + d];
}

// ---------------- generic fp32 GEMM: C[M,N] = A[M,512] * W[N,512]^T + bias ---
// 128x128 block tile, BK=8, 256 threads, 8x8 per thread.
__global__ __launch_bounds__(256)
void gemm_bias_kernel(const float* __restrict__ A,
                      const float* __restrict__ Wt,   // row n holds K contiguous
                      const float* __restrict__ bias, // may be null
                      float* __restrict__ C,
                      int M, int N, int ldc) {
    __shared__ float As[8][128];
    __shared__ float Bs[8][132];   // padded, pitch 132 floats (16B aligned)

    int bm = blockIdx.y * 128;
    int bn = blockIdx.x * 128;
    int tid = threadIdx.x;
    int tx = tid & 15;
    int ty = tid >> 4;

    int lrow = tid >> 1;            // 0..127
    int lcol = (tid & 1) * 4;       // 0 or 4

    float acc[8][8];
#pragma unroll
    for (int i = 0; i < 8; ++i)
#pragma unroll
        for (int j = 0; j < 8; ++j) acc[i][j] = 0.f;

    for (int k0 = 0; k0 < DM; k0 += 8) {
        // A tile (M divisible by 128 for all our calls)
        float4 av = *(const float4*)&A[(size_t)(bm + lrow) * DM + k0 + lcol];
        As[lcol + 0][lrow] = av.x;
        As[lcol + 1][lrow] = av.y;
        As[lcol + 2][lrow] = av.z;
        As[lcol + 3][lrow] = av.w;
        // B tile with N guard (zero-fill)
        int nrow = bn + lrow;
        float4 bv = make_float4(0.f, 0.f, 0.f, 0.f);
        if (nrow < N) bv = *(const float4*)&Wt[(size_t)nrow * DM + k0 + lcol];
        Bs[lcol + 0][lrow] = bv.x;
        Bs[lcol + 1][lrow] = bv.y;
        Bs[lcol + 2][lrow] = bv.z;
        Bs[lcol + 3][lrow] = bv.w;
        __syncthreads();
#pragma unroll
        for (int k = 0; k < 8; ++k) {
            float4 a0 = *(const float4*)&As[k][ty * 8];
            float4 a1 = *(const float4*)&As[k][ty * 8 + 4];
            float4 b0 = *(const float4*)&Bs[k][tx * 8];
            float4 b1 = *(const float4*)&Bs[k][tx * 8 + 4];
            float a[8] = {a0.x, a0.y, a0.z, a0.w, a1.x, a1.y, a1.z, a1.w};
            float b[8] = {b0.x, b0.y, b0.z, b0.w, b1.x, b1.y, b1.z, b1.w};
#pragma unroll
            for (int i = 0; i < 8; ++i)
#pragma unroll
                for (int j = 0; j < 8; ++j) acc[i][j] += a[i] * b[j];
        }
        __syncthreads();
    }

#pragma unroll
    for (int i = 0; i < 8; ++i) {
        int m = bm + ty * 8 + i;
#pragma unroll
        for (int j = 0; j < 8; ++j) {
            int n = bn + tx * 8 + j;
            if (n < N) {
                float v = acc[i][j];
                if (bias) v += bias[n];
                C[(size_t)m * ldc + n] = v;
            }
        }
    }
}

// ---------------- kernel 4: attention over gathered queries -------------------
// one block per (b, h); Q (16x64), K/V (128x64), softmax over 128 keys (no scaling)
__global__ __launch_bounds__(256)
void attn_kernel(const float* __restrict__ Q,
                 const float* __restrict__ K,
                 const float* __restrict__ V,
                 float* __restrict__ out) {
    int blk = blockIdx.x;
    int b = blk / HH, h = blk % HH;

    __shared__ float sQ[NM][DH];        // 4 KB
    __shared__ float sS[NM][SC];        // 8 KB
    __shared__ float sKV[SC][DH + 1];   // 33280 B (padded against conflicts)

    int tid = threadIdx.x;

    for (int e = tid; e < NM * DH; e += 256) {
        int m = e / DH, d0 = e % DH;
        sQ[m][d0] = Q[((size_t)b * NM + m) * DM + h * DH + d0];
    }
    for (int e = tid; e < SC * DH; e += 256) {
        int k = e / DH, d0 = e % DH;
        sKV[k][d0] = K[((size_t)b * SC + k) * DM + h * DH + d0];
    }
    __syncthreads();

    // scores = Q K^T (no 1/sqrt(dh) scaling — matches reference)
    for (int e = tid; e < NM * SC; e += 256) {
        int m = e / SC, k = e % SC;
        float acc = 0.f;
#pragma unroll
        for (int d0 = 0; d0 < DH; ++d0) acc += sQ[m][d0] * sKV[k][d0];
        sS[m][k] = acc;
    }
    __syncthreads();

    // softmax rows: warp w handles rows 2w, 2w+1
    int w = tid >> 5, lane = tid & 31;
    for (int m = 2 * w; m < 2 * w + 2; ++m) {
        float vals[4];
        float mx = -INFINITY;
#pragma unroll
        for (int j = 0; j < 4; ++j) {
            vals[j] = sS[m][lane * 4 + j];
            mx = fmaxf(mx, vals[j]);
        }
#pragma unroll
        for (int off = 16; off; off >>= 1)
            mx = fmaxf(mx, __shfl_xor_sync(0xffffffffu, mx, off));
        float sum = 0.f;
#pragma unroll
        for (int j = 0; j < 4; ++j) {
            vals[j] = expf(vals[j] - mx);
            sum += vals[j];
        }
#pragma unroll
        for (int off = 16; off; off >>= 1)
            sum += __shfl_xor_sync(0xffffffffu, sum, off);
        float inv = 1.f / sum;
#pragma unroll
        for (int j = 0; j < 4; ++j) sS[m][lane * 4 + j] = vals[j] * inv;
    }
    __syncthreads();

    // overwrite K tile with V
    for (int e = tid; e < SC * DH; e += 256) {
        int k = e / DH, d0 = e % DH;
        sKV[k][d0] = V[((size_t)b * SC + k) * DM + h * DH + d0];
    }
    __syncthreads();

    // out = P V
    for (int e = tid; e < NM * DH; e += 256) {
        int m = e / DH, d0 = e % DH;
        float acc = 0.f;
#pragma unroll
        for (int k = 0; k < SC; ++k) acc += sS[m][k] * sKV[k][d0];
        out[((size_t)b * NM + m) * DM + h * DH + d0] = acc;
    }
}

// ---------------- kernel 5: elementwise tanh ---------------------------------
__global__ void tanh_kernel(const float* __restrict__ in, float* __restrict__ out) {
    int i = blockIdx.x * blockDim.x + threadIdx.x;
    if (i < MQ * DM) out[i] = tanhf(in[i]);
}

// ---------------- kernel 7: in-place row log_softmax -------------------------
__global__ __launch_bounds__(256)
void logsoftmax_kernel(float* __restrict__ out) {
    int row = blockIdx.x;
    float* p = out + (size_t)row * NC;
    __shared__ float red[256];
    int t = threadIdx.x;

    float mx = -INFINITY;
    for (int i = t; i < NC; i += 256) mx = fmaxf(mx, p[i]);
    red[t] = mx;
    __syncthreads();
    for (int s = 128; s; s >>= 1) {
        if (t < s) red[t] = fmaxf(red[t], red[t + s]);
        __syncthreads();
    }
    mx = red[0];
    __syncthreads();

    float sum = 0.f;
    for (int i = t; i < NC; i += 256) sum += __expf(p[i] - mx);
    red[t] = sum;
    __syncthreads();
    for (int s = 128; s; s >>= 1) {
        if (t < s) red[t] += red[t + s];
        __syncthreads();
    }
    float lse = mx + logf(red[0]);
    __syncthreads();

    for (int i = t; i < NC; i += 256) p[i] = p[i] - lse;
}

// ---------------- launch -----------------------------------------------------
extern "C" void kernel_launch(void* const* d_in, const int* in_sizes, int n_in,
                              void* d_out, int out_size) {
    // metadata order:
    // 0 hist_traj_grid 1 userId 2 mask_pos 3 mask_curr_traj_grid
    // 4 aggregator_hist_traj_grid 5 emb
    // 6..11 h_* (dead) 12..17 c_wq,c_bq,c_wk,c_bk,c_wv,c_bv
    // 18..23 x_* (dead) 24 t2_w 25 t2_b
    const int*   mask_pos  = (const int*)d_in[2];
    const int*   mask_curr = (const int*)d_in[3];
    const float* emb       = (const float*)d_in[5];
    const float* c_wq = (const float*)d_in[12];
    const float* c_bq = (const float*)d_in[13];
    const float* c_wk = (const float*)d_in[14];
    const float* c_bk = (const float*)d_in[15];
    const float* c_wv = (const float*)d_in[16];
    const float* c_bv = (const float*)d_in[17];
    const float* t2_w = (const float*)d_in[24];
    const float* t2_b = (const float*)d_in[25];
    float* out = (float*)d_out;

    float *curr, *Kb, *Vb, *Qin, *Qb, *attn, *th, *hyb;
    cudaGetSymbolAddress((void**)&curr, g_curr);
    cudaGetSymbolAddress((void**)&Kb,   g_K);
    cudaGetSymbolAddress((void**)&Vb,   g_V);
    cudaGetSymbolAddress((void**)&Qin,  g_Qin);
    cudaGetSymbolAddress((void**)&Qb,   g_Q);
    cudaGetSymbolAddress((void**)&attn, g_attn);
    cudaGetSymbolAddress((void**)&th,   g_tanh);
    cudaGetSymbolAddress((void**)&hyb,  g_hyb);

    // 1. curr = emb[mask_curr] + PE
    gather_pe_kernel<<<(BB * SC * DM + 255) / 256, 256>>>(mask_curr, emb, curr);

    // 2. K, V projections over all 4096 rows
    {
        dim3 g(DM / 128, (BB * SC) / 128);
        gemm_bias_kernel<<<g, 256>>>(curr, c_wk, c_bk, Kb, BB * SC, DM, DM);
        gemm_bias_kernel<<<g, 256>>>(curr, c_wv, c_bv, Vb, BB * SC, DM, DM);
    }

    // 3. Q projection only over the 512 gathered rows
    gather_q_kernel<<<(MQ * DM + 255) / 256, 256>>>(mask_pos, curr, Qin);
    {
        dim3 g(DM / 128, MQ / 128);
        gemm_bias_kernel<<<g, 256>>>(Qin, c_wq, c_bq, Qb, MQ, DM, DM);
    }

    // 4. attention (per batch/head)
    attn_kernel<<<BB * HH, 256>>>(Qb, Kb, Vb, attn);

    // 5. hyb = tanh(attn) @ t2_w^T + t2_b
    tanh_kernel<<<(MQ * DM + 255) / 256, 256>>>(attn, th);
    {
        dim3 g(DM / 128, MQ / 128);
        gemm_bias_kernel<<<g, 256>>>(th, t2_w, t2_b, hyb, MQ, DM, DM);
    }

    // 6. scores = hyb @ emb[2:]^T  (written straight into d_out)
    {
        dim3 g((NC + 127) / 128, MQ / 128);
        gemm_bias_kernel<<<g, 256>>>(hyb, emb + 2 * DM, nullptr, out, MQ, NC, NC);
    }

    // 7. in-place log_softmax per row
    logsoftmax_kernel<<<MQ, 256>>>(out);
}

// round 2
// speedup vs baseline: 1.4469x; 1.4469x over previous
#include <cuda_runtime.h>
#include <math.h>

#define BB 32
#define SC 128
#define NM 16
#define DM 512
#define HH 8
#define DH 64
#define NC 39998
#define MQ (BB*NM)   /* 512 gathered query rows */

// ---------------- scratch (device globals; no allocation allowed) -------------
__device__ float g_curr[BB*SC*DM];
__device__ float g_K[BB*SC*DM];
__device__ float g_V[BB*SC*DM];
__device__ float g_Qin[MQ*DM];
__device__ float g_Q[MQ*DM];
__device__ float g_attn[MQ*DM];
__device__ float g_hyb[MQ*DM];

// ---------------- kernel 1: gather + positional embedding --------------------
__global__ void gather_pe_kernel(const int* __restrict__ idx,
                                 const float* __restrict__ emb,
                                 float* __restrict__ out) {
    int i = blockIdx.x * blockDim.x + threadIdx.x;
    if (i >= BB * SC * DM) return;
    int d   = i & (DM - 1);
    int row = i / DM;
    int s   = row & (SC - 1);
    int g   = idx[row];
    int i2  = d & ~1;
    float freq = expf((float)i2 * -0.0179889460176f);   // -ln(10000)/512
    float ang  = (float)s * freq;
    float pe   = (d & 1) ? cosf(ang) : sinf(ang);
    out[i] = emb[(size_t)g * DM + d] + pe;
}

// ---------------- kernel 2: gather Q input rows at mask positions ------------
__global__ void gather_q_kernel(const int* __restrict__ mask_pos,
                                const float* __restrict__ curr,
                                float* __restrict__ out) {
    int i = blockIdx.x * blockDim.x + threadIdx.x;
    if (i >= MQ * DM) return;
    int d = i & (DM - 1);
    int r = i / DM;
    int b = r / NM;
    int p = mask_pos[r];
    out[i] = curr[((size_t)b * SC + p) * DM + d];
}

// ---------------- split-TF32 helpers -----------------------------------------
__device__ __forceinline__ unsigned f2tf32(float f) {
    unsigned u;
    asm("cvt.rna.tf32.f32 %0, %1;" : "=r"(u) : "f"(f));
    return u;
}
__device__ __forceinline__ void split_tf32(float f, unsigned& hi, unsigned& lo) {
    hi = f2tf32(f);
    lo = f2tf32(f - __uint_as_float(hi));
}
__device__ __forceinline__ void mma_tf32(float* c, const unsigned* a, const unsigned* b) {
    asm("mma.sync.aligned.m16n8k8.row.col.f32.tf32.tf32.f32 "
        "{%0,%1,%2,%3}, {%4,%5,%6,%7}, {%8,%9}, {%0,%1,%2,%3};"
        : "+f"(c[0]), "+f"(c[1]), "+f"(c[2]), "+f"(c[3])
        : "r"(a[0]), "r"(a[1]), "r"(a[2]), "r"(a[3]), "r"(b[0]), "r"(b[1]));
}

// ---------------- tensor-core GEMM: C[M,N] = op(A)[M,512] @ W[N,512]^T + bias -
// 128x128 block tile, BK=32, 256 threads (8 warps, 2x4), warp tile 64x32.
// split-TF32 (3 mma products) => ~fp32 accuracy on the tensor pipe.
// a_op: 0 = identity, 1 = tanh applied to A elements while staging.
#define BK 32
#define SPITCH (BK + 4)
__global__ __launch_bounds__(256, 1)
void gemm_tc_kernel(const float* __restrict__ A,
                    const float* __restrict__ Wt,
                    const float* __restrict__ bias,
                    float* __restrict__ C,
                    int M, int N, int ldc, int a_op) {
    __shared__ float As[128][SPITCH];
    __shared__ float Bs[128][SPITCH];

    int bm = blockIdx.y * 128;
    int bn = blockIdx.x * 128;
    int tid = threadIdx.x;
    int wid = tid >> 5;
    int lane = tid & 31;
    int warp_m = wid >> 2;           // 0..1
    int warp_n = wid & 3;            // 0..3
    int g  = lane >> 2;              // 0..7
    int tg = lane & 3;               // 0..3
    int m_base = warp_m * 64;
    int n_base = warp_n * 32;

    float acc[4][4][4];
#pragma unroll
    for (int mt = 0; mt < 4; ++mt)
#pragma unroll
        for (int nt = 0; nt < 4; ++nt)
#pragma unroll
            for (int i = 0; i < 4; ++i) acc[mt][nt][i] = 0.f;

    // staging indices: 1024 float4 per tile, 4 per thread
    int f4i = tid;                    // +256 each step
    for (int k0 = 0; k0 < DM; k0 += BK) {
#pragma unroll
        for (int i = 0; i < 4; ++i) {
            int idx = f4i + i * 256;
            int row = idx >> 3;
            int c4  = (idx & 7) * 4;
            float4 av = *(const float4*)&A[(size_t)(bm + row) * DM + k0 + c4];
            if (a_op == 1) {
                av.x = tanhf(av.x); av.y = tanhf(av.y);
                av.z = tanhf(av.z); av.w = tanhf(av.w);
            }
            *(float4*)&As[row][c4] = av;
            int nrow = bn + row;
            float4 bv = make_float4(0.f, 0.f, 0.f, 0.f);
            if (nrow < N) bv = *(const float4*)&Wt[(size_t)nrow * DM + k0 + c4];
            *(float4*)&Bs[row][c4] = bv;
        }
        __syncthreads();

#pragma unroll
        for (int ks = 0; ks < 4; ++ks) {
            int kk = ks * 8;
            unsigned ahi[4][4], alo[4][4];
#pragma unroll
            for (int mt = 0; mt < 4; ++mt) {
                int r0 = m_base + mt * 16 + g;
                float f0 = As[r0][kk + tg];
                float f1 = As[r0 + 8][kk + tg];
                float f2 = As[r0][kk + tg + 4];
                float f3 = As[r0 + 8][kk + tg + 4];
                split_tf32(f0, ahi[mt][0], alo[mt][0]);
                split_tf32(f1, ahi[mt][1], alo[mt][1]);
                split_tf32(f2, ahi[mt][2], alo[mt][2]);
                split_tf32(f3, ahi[mt][3], alo[mt][3]);
            }
            unsigned bhi[4][2], blo[4][2];
#pragma unroll
            for (int nt = 0; nt < 4; ++nt) {
                int r0 = n_base + nt * 8 + g;
                float f0 = Bs[r0][kk + tg];
                float f1 = Bs[r0][kk + tg + 4];
                split_tf32(f0, bhi[nt][0], blo[nt][0]);
                split_tf32(f1, bhi[nt][1], blo[nt][1]);
            }
#pragma unroll
            for (int mt = 0; mt < 4; ++mt)
#pragma unroll
                for (int nt = 0; nt < 4; ++nt) {
                    mma_tf32(acc[mt][nt], ahi[mt], bhi[nt]);
                    mma_tf32(acc[mt][nt], alo[mt], bhi[nt]);
                    mma_tf32(acc[mt][nt], ahi[mt], blo[nt]);
                }
        }
        __syncthreads();
    }

    // epilogue
#pragma unroll
    for (int mt = 0; mt < 4; ++mt) {
        int row0 = bm + m_base + mt * 16 + g;
#pragma unroll
        for (int nt = 0; nt < 4; ++nt) {
            int col0 = bn + n_base + nt * 8 + 2 * tg;
            float b0 = 0.f, b1 = 0.f;
            if (bias) {
                if (col0 < N)     b0 = bias[col0];
                if (col0 + 1 < N) b1 = bias[col0 + 1];
            }
            if (col0 < N) {
                C[(size_t)row0 * ldc + col0] = acc[mt][nt][0] + b0;
                C[(size_t)(row0 + 8) * ldc + col0] = acc[mt][nt][2] + b0;
            }
            if (col0 + 1 < N) {
                C[(size_t)row0 * ldc + col0 + 1] = acc[mt][nt][1] + b1;
                C[(size_t)(row0 + 8) * ldc + col0 + 1] = acc[mt][nt][3] + b1;
            }
        }
    }
}

// ---------------- attention over gathered queries -----------------------------
__global__ __launch_bounds__(256)
void attn_kernel(const float* __restrict__ Q,
                 const float* __restrict__ K,
                 const float* __restrict__ V,
                 float* __restrict__ out) {
    int blk = blockIdx.x;
    int b = blk / HH, h = blk % HH;

    __shared__ float sQ[NM][DH];
    __shared__ float sS[NM][SC];
    __shared__ float sKV[SC][DH + 1];

    int tid = threadIdx.x;

    for (int e = tid; e < NM * DH; e += 256) {
        int m = e / DH, d0 = e % DH;
        sQ[m][d0] = Q[((size_t)b * NM + m) * DM + h * DH + d0];
    }
    for (int e = tid; e < SC * DH; e += 256) {
        int k = e / DH, d0 = e % DH;
        sKV[k][d0] = K[((size_t)b * SC + k) * DM + h * DH + d0];
    }
    __syncthreads();

    for (int e = tid; e < NM * SC; e += 256) {
        int m = e / SC, k = e % SC;
        float acc = 0.f;
#pragma unroll
        for (int d0 = 0; d0 < DH; ++d0) acc += sQ[m][d0] * sKV[k][d0];
        sS[m][k] = acc;
    }
    __syncthreads();

    int w = tid >> 5, lane = tid & 31;
    for (int m = 2 * w; m < 2 * w + 2; ++m) {
        float vals[4];
        float mx = -INFINITY;
#pragma unroll
        for (int j = 0; j < 4; ++j) {
            vals[j] = sS[m][lane * 4 + j];
            mx = fmaxf(mx, vals[j]);
        }
#pragma unroll
        for (int off = 16; off; off >>= 1)
            mx = fmaxf(mx, __shfl_xor_sync(0xffffffffu, mx, off));
        float sum = 0.f;
#pragma unroll
        for (int j = 0; j < 4; ++j) {
            vals[j] = expf(vals[j] - mx);
            sum += vals[j];
        }
#pragma unroll
        for (int off = 16; off; off >>= 1)
            sum += __shfl_xor_sync(0xffffffffu, sum, off);
        float inv = 1.f / sum;
#pragma unroll
        for (int j = 0; j < 4; ++j) sS[m][lane * 4 + j] = vals[j] * inv;
    }
    __syncthreads();

    for (int e = tid; e < SC * DH; e += 256) {
        int k = e / DH, d0 = e % DH;
        sKV[k][d0] = V[((size_t)b * SC + k) * DM + h * DH + d0];
    }
    __syncthreads();

    for (int e = tid; e < NM * DH; e += 256) {
        int m = e / DH, d0 = e % DH;
        float acc = 0.f;
#pragma unroll
        for (int k = 0; k < SC; ++k) acc += sS[m][k] * sKV[k][d0];
        out[((size_t)b * NM + m) * DM + h * DH + d0] = acc;
    }
}

// ---------------- in-place row log_softmax ------------------------------------
__global__ __launch_bounds__(256)
void logsoftmax_kernel(float* __restrict__ out) {
    int row = blockIdx.x;
    float* p = out + (size_t)row * NC;
    __shared__ float red[256];
    int t = threadIdx.x;

    float mx = -INFINITY;
    for (int i = t; i < NC; i += 256) mx = fmaxf(mx, p[i]);
    red[t] = mx;
    __syncthreads();
    for (int s = 128; s; s >>= 1) {
        if (t < s) red[t] = fmaxf(red[t], red[t + s]);
        __syncthreads();
    }
    mx = red[0];
    __syncthreads();

    float sum = 0.f;
    for (int i = t; i < NC; i += 256) sum += __expf(p[i] - mx);
    red[t] = sum;
    __syncthreads();
    for (int s = 128; s; s >>= 1) {
        if (t < s) red[t] += red[t + s];
        __syncthreads();
    }
    float lse = mx + logf(red[0]);
    __syncthreads();

    for (int i = t; i < NC; i += 256) p[i] = p[i] - lse;
}

// ---------------- launch -----------------------------------------------------
extern "C" void kernel_launch(void* const* d_in, const int* in_sizes, int n_in,
                              void* d_out, int out_size) {
    const int*   mask_pos  = (const int*)d_in[2];
    const int*   mask_curr = (const int*)d_in[3];
    const float* emb       = (const float*)d_in[5];
    const float* c_wq = (const float*)d_in[12];
    const float* c_bq = (const float*)d_in[13];
    const float* c_wk = (const float*)d_in[14];
    const float* c_bk = (const float*)d_in[15];
    const float* c_wv = (const float*)d_in[16];
    const float* c_bv = (const float*)d_in[17];
    const float* t2_w = (const float*)d_in[24];
    const float* t2_b = (const float*)d_in[25];
    float* out = (float*)d_out;

    float *curr, *Kb, *Vb, *Qin, *Qb, *attn, *hyb;
    cudaGetSymbolAddress((void**)&curr, g_curr);
    cudaGetSymbolAddress((void**)&Kb,   g_K);
    cudaGetSymbolAddress((void**)&Vb,   g_V);
    cudaGetSymbolAddress((void**)&Qin,  g_Qin);
    cudaGetSymbolAddress((void**)&Qb,   g_Q);
    cudaGetSymbolAddress((void**)&attn, g_attn);
    cudaGetSymbolAddress((void**)&hyb,  g_hyb);

    // 1. curr = emb[mask_curr] + PE
    gather_pe_kernel<<<(BB * SC * DM + 255) / 256, 256>>>(mask_curr, emb, curr);

    // 2. K, V projections over all 4096 rows (tensor core)
    {
        dim3 g(DM / 128, (BB * SC) / 128);
        gemm_tc_kernel<<<g, 256>>>(curr, c_wk, c_bk, Kb, BB * SC, DM, DM, 0);
        gemm_tc_kernel<<<g, 256>>>(curr, c_wv, c_bv, Vb, BB * SC, DM, DM, 0);
    }

    // 3. Q projection over the 512 gathered rows
    gather_q_kernel<<<(MQ * DM + 255) / 256, 256>>>(mask_pos, curr, Qin);
    {
        dim3 g(DM / 128, MQ / 128);
        gemm_tc_kernel<<<g, 256>>>(Qin, c_wq, c_bq, Qb, MQ, DM, DM, 0);
    }

    // 4. attention
    attn_kernel<<<BB * HH, 256>>>(Qb, Kb, Vb, attn);

    // 5. hyb = tanh(attn) @ t2_w^T + t2_b  (tanh fused into A staging)
    {
        dim3 g(DM / 128, MQ / 128);
        gemm_tc_kernel<<<g, 256>>>(attn, t2_w, t2_b, hyb, MQ, DM, DM, 1);
    }

    // 6. scores = hyb @ emb[2:]^T  (into d_out)
    {
        dim3 g((NC + 127) / 128, MQ / 128);
        gemm_tc_kernel<<<g, 256>>>(hyb, emb + 2 * DM, nullptr, out, MQ, NC, NC, 0);
    }

    // 7. in-place log_softmax
    logsoftmax_kernel<<<MQ, 256>>>(out);
}

// round 3
// speedup vs baseline: 1.6762x; 1.1585x over previous
#include <cuda_runtime.h>
#include <cuda_bf16.h>
#include <math.h>

#define BB 32
#define SC 128
#define NM 16
#define DM 512
#define HH 8
#define DH 64
#define NC 39998
#define MQ (BB*NM)   /* 512 gathered query rows */

// ---------------- scratch (device globals; no allocation allowed) -------------
__device__ float g_curr[BB*SC*DM];
__device__ float g_K[BB*SC*DM];
__device__ float g_V[BB*SC*DM];
__device__ float g_Qin[MQ*DM];
__device__ float g_Q[MQ*DM];
__device__ float g_attn[MQ*DM];
__device__ float g_hyb[MQ*DM];

// ---------------- kernel 1: gather + positional embedding --------------------
__global__ void gather_pe_kernel(const int* __restrict__ idx,
                                 const float* __restrict__ emb,
                                 float* __restrict__ out) {
    int i = blockIdx.x * blockDim.x + threadIdx.x;
    if (i >= BB * SC * DM) return;
    int d   = i & (DM - 1);
    int row = i / DM;
    int s   = row & (SC - 1);
    int g   = idx[row];
    int i2  = d & ~1;
    float freq = expf((float)i2 * -0.0179889460176f);   // -ln(10000)/512
    float ang  = (float)s * freq;
    float pe   = (d & 1) ? cosf(ang) : sinf(ang);
    out[i] = emb[(size_t)g * DM + d] + pe;
}

// ---------------- kernel 2: gather Q input rows at mask positions ------------
__global__ void gather_q_kernel(const int* __restrict__ mask_pos,
                                const float* __restrict__ curr,
                                float* __restrict__ out) {
    int i = blockIdx.x * blockDim.x + threadIdx.x;
    if (i >= MQ * DM) return;
    int d = i & (DM - 1);
    int r = i / DM;
    int b = r / NM;
    int p = mask_pos[r];
    out[i] = curr[((size_t)b * SC + p) * DM + d];
}

// ---------------- bf16 split helpers -----------------------------------------
__device__ __forceinline__ void split_pack(float x, float y,
                                           unsigned& hi, unsigned& lo) {
    __nv_bfloat16 hx = __float2bfloat16_rn(x);
    __nv_bfloat16 hy = __float2bfloat16_rn(y);
    float rx = x - __bfloat162float(hx);
    float ry = y - __bfloat162float(hy);
    __nv_bfloat16 lx = __float2bfloat16_rn(rx);
    __nv_bfloat16 ly = __float2bfloat16_rn(ry);
    hi = ((unsigned)__bfloat16_as_ushort(hy) << 16) | __bfloat16_as_ushort(hx);
    lo = ((unsigned)__bfloat16_as_ushort(ly) << 16) | __bfloat16_as_ushort(lx);
}

__device__ __forceinline__ void mma_bf16(float* c, const unsigned* a, const unsigned* b) {
    asm("mma.sync.aligned.m16n8k16.row.col.f32.bf16.bf16.f32 "
        "{%0,%1,%2,%3}, {%4,%5,%6,%7}, {%8,%9}, {%0,%1,%2,%3};"
        : "+f"(c[0]), "+f"(c[1]), "+f"(c[2]), "+f"(c[3])
        : "r"(a[0]), "r"(a[1]), "r"(a[2]), "r"(a[3]), "r"(b[0]), "r"(b[1]));
}

// ---------------- tensor-core GEMM: C[M,N] = op(A)[M,512] @ W[N,512]^T + bias -
// 128x128 block tile, BK=32, 256 threads (8 warps, 2x4), warp tile 64x32.
// bf16x3 split (hi*hi + hi*lo + lo*hi), packed bf16x2 smem, convert-at-staging.
#define BK 32
#define PKP 20   /* packed pitch in uint32 (16 pairs + 4 pad) -> conflict-free */
__global__ __launch_bounds__(256)
void gemm_tc_kernel(const float* __restrict__ A,
                    const float* __restrict__ Wt,
                    const float* __restrict__ bias,
                    float* __restrict__ C,
                    int M, int N, int ldc, int a_op) {
    __shared__ unsigned AsH[128][PKP];
    __shared__ unsigned AsL[128][PKP];
    __shared__ unsigned BsH[128][PKP];
    __shared__ unsigned BsL[128][PKP];

    int bm = blockIdx.y * 128;
    int bn = blockIdx.x * 128;
    int tid = threadIdx.x;
    int wid = tid >> 5;
    int lane = tid & 31;
    int warp_m = wid >> 2;           // 0..1
    int warp_n = wid & 3;            // 0..3
    int g  = lane >> 2;              // 0..7
    int tg = lane & 3;               // 0..3
    int m_base = warp_m * 64;
    int n_base = warp_n * 32;

    float acc[4][4][4];
#pragma unroll
    for (int mt = 0; mt < 4; ++mt)
#pragma unroll
        for (int nt = 0; nt < 4; ++nt)
#pragma unroll
            for (int i = 0; i < 4; ++i) acc[mt][nt][i] = 0.f;

    for (int k0 = 0; k0 < DM; k0 += BK) {
        // stage + split-convert: 1024 float4 per operand tile, 4 per thread
#pragma unroll
        for (int i = 0; i < 4; ++i) {
            int idx = tid + i * 256;
            int row = idx >> 3;
            int p   = (idx & 7) * 2;           // packed-pair column base
            float4 av = *(const float4*)&A[(size_t)(bm + row) * DM + k0 + p * 2];
            if (a_op == 1) {
                av.x = tanhf(av.x); av.y = tanhf(av.y);
                av.z = tanhf(av.z); av.w = tanhf(av.w);
            }
            split_pack(av.x, av.y, AsH[row][p],     AsL[row][p]);
            split_pack(av.z, av.w, AsH[row][p + 1], AsL[row][p + 1]);

            int nrow = bn + row;
            float4 bv = make_float4(0.f, 0.f, 0.f, 0.f);
            if (nrow < N) bv = *(const float4*)&Wt[(size_t)nrow * DM + k0 + p * 2];
            split_pack(bv.x, bv.y, BsH[row][p],     BsL[row][p]);
            split_pack(bv.z, bv.w, BsH[row][p + 1], BsL[row][p + 1]);
        }
        __syncthreads();

#pragma unroll
        for (int ks = 0; ks < 2; ++ks) {       // two 16-k chunks per BK=32
            int kc = ks * 8;                   // pair offset
            unsigned ah[4][4], al[4][4];
#pragma unroll
            for (int mt = 0; mt < 4; ++mt) {
                int r0 = m_base + mt * 16 + g;
                ah[mt][0] = AsH[r0][kc + tg];
                ah[mt][1] = AsH[r0 + 8][kc + tg];
                ah[mt][2] = AsH[r0][kc + tg + 4];
                ah[mt][3] = AsH[r0 + 8][kc + tg + 4];
                al[mt][0] = AsL[r0][kc + tg];
                al[mt][1] = AsL[r0 + 8][kc + tg];
                al[mt][2] = AsL[r0][kc + tg + 4];
                al[mt][3] = AsL[r0 + 8][kc + tg + 4];
            }
            unsigned bh[4][2], bl[4][2];
#pragma unroll
            for (int nt = 0; nt < 4; ++nt) {
                int r0 = n_base + nt * 8 + g;
                bh[nt][0] = BsH[r0][kc + tg];
                bh[nt][1] = BsH[r0][kc + tg + 4];
                bl[nt][0] = BsL[r0][kc + tg];
                bl[nt][1] = BsL[r0][kc + tg + 4];
            }
#pragma unroll
            for (int mt = 0; mt < 4; ++mt)
#pragma unroll
                for (int nt = 0; nt < 4; ++nt) {
                    mma_bf16(acc[mt][nt], ah[mt], bh[nt]);
                    mma_bf16(acc[mt][nt], al[mt], bh[nt]);
                    mma_bf16(acc[mt][nt], ah[mt], bl[nt]);
                }
        }
        __syncthreads();
    }

    // epilogue: c0=(g,2tg) c1=(g,2tg+1) c2=(g+8,2tg) c3=(g+8,2tg+1)
#pragma unroll
    for (int mt = 0; mt < 4; ++mt) {
        int row0 = bm + m_base + mt * 16 + g;
#pragma unroll
        for (int nt = 0; nt < 4; ++nt) {
            int col0 = bn + n_base + nt * 8 + 2 * tg;
            float b0 = 0.f, b1 = 0.f;
            if (bias) {
                if (col0 < N)     b0 = bias[col0];
                if (col0 + 1 < N) b1 = bias[col0 + 1];
            }
            if (col0 < N) {
                C[(size_t)row0 * ldc + col0]       = acc[mt][nt][0] + b0;
                C[(size_t)(row0 + 8) * ldc + col0] = acc[mt][nt][2] + b0;
            }
            if (col0 + 1 < N) {
                C[(size_t)row0 * ldc + col0 + 1]       = acc[mt][nt][1] + b1;
                C[(size_t)(row0 + 8) * ldc + col0 + 1] = acc[mt][nt][3] + b1;
            }
        }
    }
}

// ---------------- attention over gathered queries -----------------------------
__global__ __launch_bounds__(256)
void attn_kernel(const float* __restrict__ Q,
                 const float* __restrict__ K,
                 const float* __restrict__ V,
                 float* __restrict__ out) {
    int blk = blockIdx.x;
    int b = blk / HH, h = blk % HH;

    __shared__ float sQ[NM][DH];
    __shared__ float sS[NM][SC];
    __shared__ float sKV[SC][DH + 1];

    int tid = threadIdx.x;

    for (int e = tid; e < NM * DH; e += 256) {
        int m = e / DH, d0 = e % DH;
        sQ[m][d0] = Q[((size_t)b * NM + m) * DM + h * DH + d0];
    }
    for (int e = tid; e < SC * DH; e += 256) {
        int k = e / DH, d0 = e % DH;
        sKV[k][d0] = K[((size_t)b * SC + k) * DM + h * DH + d0];
    }
    __syncthreads();

    for (int e = tid; e < NM * SC; e += 256) {
        int m = e / SC, k = e % SC;
        float acc = 0.f;
#pragma unroll
        for (int d0 = 0; d0 < DH; ++d0) acc += sQ[m][d0] * sKV[k][d0];
        sS[m][k] = acc;
    }
    __syncthreads();

    int w = tid >> 5, lane = tid & 31;
    for (int m = 2 * w; m < 2 * w + 2; ++m) {
        float vals[4];
        float mx = -INFINITY;
#pragma unroll
        for (int j = 0; j < 4; ++j) {
            vals[j] = sS[m][lane * 4 + j];
            mx = fmaxf(mx, vals[j]);
        }
#pragma unroll
        for (int off = 16; off; off >>= 1)
            mx = fmaxf(mx, __shfl_xor_sync(0xffffffffu, mx, off));
        float sum = 0.f;
#pragma unroll
        for (int j = 0; j < 4; ++j) {
            vals[j] = expf(vals[j] - mx);
            sum += vals[j];
        }
#pragma unroll
        for (int off = 16; off; off >>= 1)
            sum += __shfl_xor_sync(0xffffffffu, sum, off);
        float inv = 1.f / sum;
#pragma unroll
        for (int j = 0; j < 4; ++j) sS[m][lane * 4 + j] = vals[j] * inv;
    }
    __syncthreads();

    for (int e = tid; e < SC * DH; e += 256) {
        int k = e / DH, d0 = e % DH;
        sKV[k][d0] = V[((size_t)b * SC + k) * DM + h * DH + d0];
    }
    __syncthreads();

    for (int e = tid; e < NM * DH; e += 256) {
        int m = e / DH, d0 = e % DH;
        float acc = 0.f;
#pragma unroll
        for (int k = 0; k < SC; ++k) acc += sS[m][k] * sKV[k][d0];
        out[((size_t)b * NM + m) * DM + h * DH + d0] = acc;
    }
}

// ---------------- in-place row log_softmax (online max+sum, 2 passes) ---------
__global__ __launch_bounds__(256)
void logsoftmax_kernel(float* __restrict__ out) {
    int row = blockIdx.x;
    float* p = out + (size_t)row * NC;
    __shared__ float rm[256], rs[256];
    int t = threadIdx.x;

    float m = -INFINITY, s = 0.f;
    for (int i = t; i < NC; i += 256) {
        float v = p[i];
        float nm = fmaxf(m, v);
        s = s * __expf(m - nm) + __expf(v - nm);
        m = nm;
    }
    rm[t] = m; rs[t] = s;
    __syncthreads();
    for (int st = 128; st; st >>= 1) {
        if (t < st) {
            float m2 = rm[t + st], s2 = rs[t + st];
            float nm = fmaxf(rm[t], m2);
            rs[t] = rs[t] * __expf(rm[t] - nm) + s2 * __expf(m2 - nm);
            rm[t] = nm;
        }
        __syncthreads();
    }
    float lse = rm[0] + logf(rs[0]);
    __syncthreads();

    for (int i = t; i < NC; i += 256) p[i] = p[i] - lse;
}

// ---------------- launch -----------------------------------------------------
extern "C" void kernel_launch(void* const* d_in, const int* in_sizes, int n_in,
                              void* d_out, int out_size) {
    const int*   mask_pos  = (const int*)d_in[2];
    const int*   mask_curr = (const int*)d_in[3];
    const float* emb       = (const float*)d_in[5];
    const float* c_wq = (const float*)d_in[12];
    const float* c_bq = (const float*)d_in[13];
    const float* c_wk = (const float*)d_in[14];
    const float* c_bk = (const float*)d_in[15];
    const float* c_wv = (const float*)d_in[16];
    const float* c_bv = (const float*)d_in[17];
    const float* t2_w = (const float*)d_in[24];
    const float* t2_b = (const float*)d_in[25];
    float* out = (float*)d_out;

    float *curr, *Kb, *Vb, *Qin, *Qb, *attn, *hyb;
    cudaGetSymbolAddress((void**)&curr, g_curr);
    cudaGetSymbolAddress((void**)&Kb,   g_K);
    cudaGetSymbolAddress((void**)&Vb,   g_V);
    cudaGetSymbolAddress((void**)&Qin,  g_Qin);
    cudaGetSymbolAddress((void**)&Qb,   g_Q);
    cudaGetSymbolAddress((void**)&attn, g_attn);
    cudaGetSymbolAddress((void**)&hyb,  g_hyb);

    // 1. curr = emb[mask_curr] + PE
    gather_pe_kernel<<<(BB * SC * DM + 255) / 256, 256>>>(mask_curr, emb, curr);

    // 2. K, V projections over all 4096 rows
    {
        dim3 g(DM / 128, (BB * SC) / 128);
        gemm_tc_kernel<<<g, 256>>>(curr, c_wk, c_bk, Kb, BB * SC, DM, DM, 0);
        gemm_tc_kernel<<<g, 256>>>(curr, c_wv, c_bv, Vb, BB * SC, DM, DM, 0);
    }

    // 3. Q projection over the 512 gathered rows
    gather_q_kernel<<<(MQ * DM + 255) / 256, 256>>>(mask_pos, curr, Qin);
    {
        dim3 g(DM / 128, MQ / 128);
        gemm_tc_kernel<<<g, 256>>>(Qin, c_wq, c_bq, Qb, MQ, DM, DM, 0);
    }

    // 4. attention
    attn_kernel<<<BB * HH, 256>>>(Qb, Kb, Vb, attn);

    // 5. hyb = tanh(attn) @ t2_w^T + t2_b  (tanh fused into A staging)
    {
        dim3 g(DM / 128, MQ / 128);
        gemm_tc_kernel<<<g, 256>>>(attn, t2_w, t2_b, hyb, MQ, DM, DM, 1);
    }

    // 6. scores = hyb @ emb[2:]^T  (into d_out)
    {
        dim3 g((NC + 127) / 128, MQ / 128);
        gemm_tc_kernel<<<g, 256>>>(hyb, emb + 2 * DM, nullptr, out, MQ, NC, NC, 0);
    }

    // 7. in-place log_softmax
    logsoftmax_kernel<<<MQ, 256>>>(out);
}

// round 4
// speedup vs baseline: 2.3487x; 1.4012x over previous
#include <cuda_runtime.h>
#include <cuda_bf16.h>
#include <math.h>

#define BB 32
#define SC 128
#define NM 16
#define DM 512
#define HH 8
#define DH 64
#define NC 39998
#define MQ (BB*NM)   /* 512 gathered query rows */
#define KP2 256      /* packed pairs per row (DM/2) */

// ---------------- scratch (device globals; no allocation allowed) -------------
__device__ float g_curr[BB*SC*DM];
__device__ float g_K[BB*SC*DM];
__device__ float g_V[BB*SC*DM];
__device__ float g_Qin[MQ*DM];
__device__ float g_Q[MQ*DM];
__device__ float g_attn[MQ*DM];
__device__ float g_hyb[MQ*DM];

// packed bf16 hi/lo operands
__device__ unsigned g_pk_embH[(size_t)NC*KP2];
__device__ unsigned g_pk_embL[(size_t)NC*KP2];
__device__ unsigned g_pk_currH[BB*SC*KP2];
__device__ unsigned g_pk_currL[BB*SC*KP2];
__device__ unsigned g_pk_wH[4*DM*KP2];   // wk, wv, wq, t2w
__device__ unsigned g_pk_wL[4*DM*KP2];
__device__ unsigned g_pk_qinH[MQ*KP2];
__device__ unsigned g_pk_qinL[MQ*KP2];
__device__ unsigned g_pk_tanhH[MQ*KP2];
__device__ unsigned g_pk_tanhL[MQ*KP2];
__device__ unsigned g_pk_hybH[MQ*KP2];
__device__ unsigned g_pk_hybL[MQ*KP2];

// ---------------- bf16 split helper ------------------------------------------
__device__ __forceinline__ void split_pack(float x, float y,
                                           unsigned& hi, unsigned& lo) {
    __nv_bfloat16 hx = __float2bfloat16_rn(x);
    __nv_bfloat16 hy = __float2bfloat16_rn(y);
    float rx = x - __bfloat162float(hx);
    float ry = y - __bfloat162float(hy);
    __nv_bfloat16 lx = __float2bfloat16_rn(rx);
    __nv_bfloat16 ly = __float2bfloat16_rn(ry);
    hi = ((unsigned)__bfloat16_as_ushort(hy) << 16) | __bfloat16_as_ushort(hx);
    lo = ((unsigned)__bfloat16_as_ushort(ly) << 16) | __bfloat16_as_ushort(lx);
}

// ---------------- kernel: gather + positional embedding ----------------------
__global__ void gather_pe_kernel(const int* __restrict__ idx,
                                 const float* __restrict__ emb,
                                 float* __restrict__ out) {
    int i = blockIdx.x * blockDim.x + threadIdx.x;
    if (i >= BB * SC * DM) return;
    int d   = i & (DM - 1);
    int row = i / DM;
    int s   = row & (SC - 1);
    int g   = idx[row];
    int i2  = d & ~1;
    float freq = expf((float)i2 * -0.0179889460176f);   // -ln(10000)/512
    float ang  = (float)s * freq;
    float pe   = (d & 1) ? cosf(ang) : sinf(ang);
    out[i] = emb[(size_t)g * DM + d] + pe;
}

// ---------------- kernel: gather Q input rows --------------------------------
__global__ void gather_q_kernel(const int* __restrict__ mask_pos,
                                const float* __restrict__ curr,
                                float* __restrict__ out) {
    int i = blockIdx.x * blockDim.x + threadIdx.x;
    if (i >= MQ * DM) return;
    int d = i & (DM - 1);
    int r = i / DM;
    int b = r / NM;
    int p = mask_pos[r];
    out[i] = curr[((size_t)b * SC + p) * DM + d];
}

// ---------------- kernel: prepack float -> packed bf16 hi/lo ------------------
__global__ void prepack_kernel(const float* __restrict__ in,
                               unsigned* __restrict__ H,
                               unsigned* __restrict__ L,
                               long npairs, int do_tanh) {
    long i = (long)blockIdx.x * blockDim.x + threadIdx.x;
    if (i >= npairs) return;
    float2 v = ((const float2*)in)[i];
    if (do_tanh) { v.x = tanhf(v.x); v.y = tanhf(v.y); }
    split_pack(v.x, v.y, H[i], L[i]);
}

// ---------------- mma + cp.async helpers --------------------------------------
__device__ __forceinline__ void mma_bf16(float* c, const unsigned* a, const unsigned* b) {
    asm("mma.sync.aligned.m16n8k16.row.col.f32.bf16.bf16.f32 "
        "{%0,%1,%2,%3}, {%4,%5,%6,%7}, {%8,%9}, {%0,%1,%2,%3};"
        : "+f"(c[0]), "+f"(c[1]), "+f"(c[2]), "+f"(c[3])
        : "r"(a[0]), "r"(a[1]), "r"(a[2]), "r"(a[3]), "r"(b[0]), "r"(b[1]));
}
__device__ __forceinline__ void cp16(unsigned* dst, const unsigned* src, bool ok) {
    unsigned d = (unsigned)__cvta_generic_to_shared(dst);
    int sz = ok ? 16 : 0;
    asm volatile("cp.async.cg.shared.global [%0], [%1], 16, %2;"
                 :: "r"(d), "l"(src), "r"(sz));
}

// ---------------- prepacked tensor-core GEMM ----------------------------------
// C[M,N] = A[M,512] @ B[N,512]^T + bias, A/B prepacked bf16 hi/lo pairs.
// grid: (M/128, ceil(N/128)) — M fastest so M-blocks share B tiles via L2.
// 128x128 block tile, BK=32 (16 pairs), 8 warps 64x32, bf16x3, double-buffered
// cp.async staging.
#define PITCH 20
#define TSZ (128*PITCH)
__global__ __launch_bounds__(256)
void gemm_pk_kernel(const unsigned* __restrict__ AH, const unsigned* __restrict__ AL,
                    const unsigned* __restrict__ BH, const unsigned* __restrict__ BL,
                    const float* __restrict__ bias,
                    float* __restrict__ C,
                    int M, int N, int ldc) {
    extern __shared__ unsigned sm[];

    int bm = blockIdx.x * 128;
    int bn = blockIdx.y * 128;
    int tid = threadIdx.x;
    int wid = tid >> 5;
    int lane = tid & 31;
    int warp_m = wid >> 2;           // 0..1
    int warp_n = wid & 3;            // 0..3
    int g  = lane >> 2;              // 0..7
    int tg = lane & 3;               // 0..3
    int m_base = warp_m * 64;
    int n_base = warp_n * 32;

    float acc[4][4][4];
#pragma unroll
    for (int mt = 0; mt < 4; ++mt)
#pragma unroll
        for (int nt = 0; nt < 4; ++nt)
#pragma unroll
            for (int i = 0; i < 4; ++i) acc[mt][nt][i] = 0.f;

    // staging: each tile is 128 rows x 16 uint32 per array; 512 uint4 per array;
    // per thread: 2 chunks x 4 arrays = 8 cp.async of 16B.
    int srow0 = tid >> 2;            // chunk 0 row
    int sc4   = (tid & 3) * 4;       // uint32 col within 16
    int srow1 = (tid + 256) >> 2;    // chunk 1 row

#define STAGE(buf, k0p)                                                          \
    {                                                                            \
        unsigned* bAH = sm + (buf) * 4 * TSZ;                                    \
        unsigned* bAL = bAH + TSZ;                                               \
        unsigned* bBH = bAH + 2 * TSZ;                                           \
        unsigned* bBL = bAH + 3 * TSZ;                                           \
        _Pragma("unroll")                                                        \
        for (int i = 0; i < 2; ++i) {                                            \
            int row = i ? srow1 : srow0;                                         \
            const unsigned* aH = AH + (size_t)(bm + row) * KP2 + (k0p) + sc4;    \
            const unsigned* aL = AL + (size_t)(bm + row) * KP2 + (k0p) + sc4;    \
            cp16(bAH + row * PITCH + sc4, aH, true);                             \
            cp16(bAL + row * PITCH + sc4, aL, true);                             \
            int nrow = bn + row;                                                 \
            bool ok = nrow < N;                                                  \
            int nrc = ok ? nrow : 0;                                             \
            const unsigned* bH = BH + (size_t)nrc * KP2 + (k0p) + sc4;           \
            const unsigned* bL = BL + (size_t)nrc * KP2 + (k0p) + sc4;           \
            cp16(bBH + row * PITCH + sc4, bH, ok);                               \
            cp16(bBL + row * PITCH + sc4, bL, ok);                               \
        }                                                                        \
    }

    STAGE(0, 0);
    asm volatile("cp.async.commit_group;");

    const int NSTEP = DM / 32;       // 16
    for (int s = 0; s < NSTEP; ++s) {
        if (s + 1 < NSTEP) {
            STAGE((s + 1) & 1, (s + 1) * 16);
            asm volatile("cp.async.commit_group;");
            asm volatile("cp.async.wait_group 1;");
        } else {
            asm volatile("cp.async.wait_group 0;");
        }
        __syncthreads();

        unsigned* AsH = sm + (s & 1) * 4 * TSZ;
        unsigned* AsL = AsH + TSZ;
        unsigned* BsH = AsH + 2 * TSZ;
        unsigned* BsL = AsH + 3 * TSZ;

#pragma unroll
        for (int ks = 0; ks < 2; ++ks) {
            int kc = ks * 8;
            unsigned ah[4][4], al[4][4];
#pragma unroll
            for (int mt = 0; mt < 4; ++mt) {
                int r0 = m_base + mt * 16 + g;
                ah[mt][0] = AsH[r0 * PITCH + kc + tg];
                ah[mt][1] = AsH[(r0 + 8) * PITCH + kc + tg];
                ah[mt][2] = AsH[r0 * PITCH + kc + tg + 4];
                ah[mt][3] = AsH[(r0 + 8) * PITCH + kc + tg + 4];
                al[mt][0] = AsL[r0 * PITCH + kc + tg];
                al[mt][1] = AsL[(r0 + 8) * PITCH + kc + tg];
                al[mt][2] = AsL[r0 * PITCH + kc + tg + 4];
                al[mt][3] = AsL[(r0 + 8) * PITCH + kc + tg + 4];
            }
            unsigned bh[4][2], bl[4][2];
#pragma unroll
            for (int nt = 0; nt < 4; ++nt) {
                int r0 = n_base + nt * 8 + g;
                bh[nt][0] = BsH[r0 * PITCH + kc + tg];
                bh[nt][1] = BsH[r0 * PITCH + kc + tg + 4];
                bl[nt][0] = BsL[r0 * PITCH + kc + tg];
                bl[nt][1] = BsL[r0 * PITCH + kc + tg + 4];
            }
#pragma unroll
            for (int mt = 0; mt < 4; ++mt)
#pragma unroll
                for (int nt = 0; nt < 4; ++nt) {
                    mma_bf16(acc[mt][nt], ah[mt], bh[nt]);
                    mma_bf16(acc[mt][nt], al[mt], bh[nt]);
                    mma_bf16(acc[mt][nt], ah[mt], bl[nt]);
                }
        }
        __syncthreads();
    }

    // epilogue: c0=(g,2tg) c1=(g,2tg+1) c2=(g+8,2tg) c3=(g+8,2tg+1)
#pragma unroll
    for (int mt = 0; mt < 4; ++mt) {
        int row0 = bm + m_base + mt * 16 + g;
#pragma unroll
        for (int nt = 0; nt < 4; ++nt) {
            int col0 = bn + n_base + nt * 8 + 2 * tg;
            float b0 = 0.f, b1 = 0.f;
            if (bias) {
                if (col0 < N)     b0 = bias[col0];
                if (col0 + 1 < N) b1 = bias[col0 + 1];
            }
            if (col0 < N) {
                C[(size_t)row0 * ldc + col0]       = acc[mt][nt][0] + b0;
                C[(size_t)(row0 + 8) * ldc + col0] = acc[mt][nt][2] + b0;
            }
            if (col0 + 1 < N) {
                C[(size_t)row0 * ldc + col0 + 1]       = acc[mt][nt][1] + b1;
                C[(size_t)(row0 + 8) * ldc + col0 + 1] = acc[mt][nt][3] + b1;
            }
        }
    }
}

// ---------------- attention over gathered queries -----------------------------
__global__ __launch_bounds__(256)
void attn_kernel(const float* __restrict__ Q,
                 const float* __restrict__ K,
                 const float* __restrict__ V,
                 float* __restrict__ out) {
    int blk = blockIdx.x;
    int b = blk / HH, h = blk % HH;

    __shared__ float sQ[NM][DH];
    __shared__ float sS[NM][SC];
    __shared__ float sKV[SC][DH + 1];

    int tid = threadIdx.x;

    for (int e = tid; e < NM * DH; e += 256) {
        int m = e / DH, d0 = e % DH;
        sQ[m][d0] = Q[((size_t)b * NM + m) * DM + h * DH + d0];
    }
    for (int e = tid; e < SC * DH; e += 256) {
        int k = e / DH, d0 = e % DH;
        sKV[k][d0] = K[((size_t)b * SC + k) * DM + h * DH + d0];
    }
    __syncthreads();

    for (int e = tid; e < NM * SC; e += 256) {
        int m = e / SC, k = e % SC;
        float acc = 0.f;
#pragma unroll
        for (int d0 = 0; d0 < DH; ++d0) acc += sQ[m][d0] * sKV[k][d0];
        sS[m][k] = acc;
    }
    __syncthreads();

    int w = tid >> 5, lane = tid & 31;
    for (int m = 2 * w; m < 2 * w + 2; ++m) {
        float vals[4];
        float mx = -INFINITY;
#pragma unroll
        for (int j = 0; j < 4; ++j) {
            vals[j] = sS[m][lane * 4 + j];
            mx = fmaxf(mx, vals[j]);
        }
#pragma unroll
        for (int off = 16; off; off >>= 1)
            mx = fmaxf(mx, __shfl_xor_sync(0xffffffffu, mx, off));
        float sum = 0.f;
#pragma unroll
        for (int j = 0; j < 4; ++j) {
            vals[j] = expf(vals[j] - mx);
            sum += vals[j];
        }
#pragma unroll
        for (int off = 16; off; off >>= 1)
            sum += __shfl_xor_sync(0xffffffffu, sum, off);
        float inv = 1.f / sum;
#pragma unroll
        for (int j = 0; j < 4; ++j) sS[m][lane * 4 + j] = vals[j] * inv;
    }
    __syncthreads();

    for (int e = tid; e < SC * DH; e += 256) {
        int k = e / DH, d0 = e % DH;
        sKV[k][d0] = V[((size_t)b * SC + k) * DM + h * DH + d0];
    }
    __syncthreads();

    for (int e = tid; e < NM * DH; e += 256) {
        int m = e / DH, d0 = e % DH;
        float acc = 0.f;
#pragma unroll
        for (int k = 0; k < SC; ++k) acc += sS[m][k] * sKV[k][d0];
        out[((size_t)b * NM + m) * DM + h * DH + d0] = acc;
    }
}

// ---------------- in-place row log_softmax (online max+sum, 2 passes) ---------
__global__ __launch_bounds__(256)
void logsoftmax_kernel(float* __restrict__ out) {
    int row = blockIdx.x;
    float* p = out + (size_t)row * NC;
    __shared__ float rm[256], rs[256];
    int t = threadIdx.x;

    float m = -INFINITY, s = 0.f;
    for (int i = t; i < NC; i += 256) {
        float v = p[i];
        float nm = fmaxf(m, v);
        s = s * __expf(m - nm) + __expf(v - nm);
        m = nm;
    }
    rm[t] = m; rs[t] = s;
    __syncthreads();
    for (int st = 128; st; st >>= 1) {
        if (t < st) {
            float m2 = rm[t + st], s2 = rs[t + st];
            float nm = fmaxf(rm[t], m2);
            rs[t] = rs[t] * __expf(rm[t] - nm) + s2 * __expf(m2 - nm);
            rm[t] = nm;
        }
        __syncthreads();
    }
    float lse = rm[0] + logf(rs[0]);
    __syncthreads();

    for (int i = t; i < NC; i += 256) p[i] = p[i] - lse;
}

// ---------------- launch -----------------------------------------------------
extern "C" void kernel_launch(void* const* d_in, const int* in_sizes, int n_in,
                              void* d_out, int out_size) {
    const int*   mask_pos  = (const int*)d_in[2];
    const int*   mask_curr = (const int*)d_in[3];
    const float* emb       = (const float*)d_in[5];
    const float* c_wq = (const float*)d_in[12];
    const float* c_bq = (const float*)d_in[13];
    const float* c_wk = (const float*)d_in[14];
    const float* c_bk = (const float*)d_in[15];
    const float* c_wv = (const float*)d_in[16];
    const float* c_bv = (const float*)d_in[17];
    const float* t2_w = (const float*)d_in[24];
    const float* t2_b = (const float*)d_in[25];
    float* out = (float*)d_out;

    float *curr, *Kb, *Vb, *Qin, *Qb, *attn, *hyb;
    cudaGetSymbolAddress((void**)&curr, g_curr);
    cudaGetSymbolAddress((void**)&Kb,   g_K);
    cudaGetSymbolAddress((void**)&Vb,   g_V);
    cudaGetSymbolAddress((void**)&Qin,  g_Qin);
    cudaGetSymbolAddress((void**)&Qb,   g_Q);
    cudaGetSymbolAddress((void**)&attn, g_attn);
    cudaGetSymbolAddress((void**)&hyb,  g_hyb);

    unsigned *embH, *embL, *currH, *currL, *wH, *wL;
    unsigned *qinH, *qinL, *tanhH, *tanhL, *hybH, *hybL;
    cudaGetSymbolAddress((void**)&embH,  g_pk_embH);
    cudaGetSymbolAddress((void**)&embL,  g_pk_embL);
    cudaGetSymbolAddress((void**)&currH, g_pk_currH);
    cudaGetSymbolAddress((void**)&currL, g_pk_currL);
    cudaGetSymbolAddress((void**)&wH,    g_pk_wH);
    cudaGetSymbolAddress((void**)&wL,    g_pk_wL);
    cudaGetSymbolAddress((void**)&qinH,  g_pk_qinH);
    cudaGetSymbolAddress((void**)&qinL,  g_pk_qinL);
    cudaGetSymbolAddress((void**)&tanhH, g_pk_tanhH);
    cudaGetSymbolAddress((void**)&tanhL, g_pk_tanhL);
    cudaGetSymbolAddress((void**)&hybH,  g_pk_hybH);
    cudaGetSymbolAddress((void**)&hybL,  g_pk_hybL);

    cudaFuncSetAttribute(gemm_pk_kernel,
                         cudaFuncAttributeMaxDynamicSharedMemorySize, 2 * 4 * TSZ * 4);
    const int SMEMB = 2 * 4 * TSZ * 4;   // 81920 bytes

    const long WP = (long)DM * KP2;      // pairs per 512x512 matrix

    // 1. curr = emb[mask_curr] + PE
    gather_pe_kernel<<<(BB * SC * DM + 255) / 256, 256>>>(mask_curr, emb, curr);

    // 2. prepack operands (weights + emb can go in parallel with nothing else pending)
    prepack_kernel<<<(int)((WP + 255) / 256), 256>>>(c_wk, wH,          wL,          WP, 0);
    prepack_kernel<<<(int)((WP + 255) / 256), 256>>>(c_wv, wH + WP,     wL + WP,     WP, 0);
    prepack_kernel<<<(int)((WP + 255) / 256), 256>>>(c_wq, wH + 2 * WP, wL + 2 * WP, WP, 0);
    prepack_kernel<<<(int)((WP + 255) / 256), 256>>>(t2_w, wH + 3 * WP, wL + 3 * WP, WP, 0);
    {
        long np = (long)NC * KP2;
        prepack_kernel<<<(int)((np + 255) / 256), 256>>>(emb + 2 * DM, embH, embL, np, 0);
    }
    {
        long np = (long)BB * SC * KP2;
        prepack_kernel<<<(int)((np + 255) / 256), 256>>>(curr, currH, currL, np, 0);
    }

    // 3. K, V projections over all 4096 rows
    {
        dim3 g((BB * SC) / 128, DM / 128);
        gemm_pk_kernel<<<g, 256, SMEMB>>>(currH, currL, wH,      wL,      c_bk, Kb, BB * SC, DM, DM);
        gemm_pk_kernel<<<g, 256, SMEMB>>>(currH, currL, wH + WP, wL + WP, c_bv, Vb, BB * SC, DM, DM);
    }

    // 4. Q projection over the 512 gathered rows
    gather_q_kernel<<<(MQ * DM + 255) / 256, 256>>>(mask_pos, curr, Qin);
    prepack_kernel<<<(MQ * KP2 + 255) / 256, 256>>>(Qin, qinH, qinL, MQ * KP2, 0);
    {
        dim3 g(MQ / 128, DM / 128);
        gemm_pk_kernel<<<g, 256, SMEMB>>>(qinH, qinL, wH + 2 * WP, wL + 2 * WP, c_bq, Qb, MQ, DM, DM);
    }

    // 5. attention
    attn_kernel<<<BB * HH, 256>>>(Qb, Kb, Vb, attn);

    // 6. hyb = tanh(attn) @ t2_w^T + t2_b  (tanh fused into prepack)
    prepack_kernel<<<(MQ * KP2 + 255) / 256, 256>>>(attn, tanhH, tanhL, MQ * KP2, 1);
    {
        dim3 g(MQ / 128, DM / 128);
        gemm_pk_kernel<<<g, 256, SMEMB>>>(tanhH, tanhL, wH + 3 * WP, wL + 3 * WP, t2_b, hyb, MQ, DM, DM);
    }

    // 7. scores = hyb @ emb[2:]^T  (into d_out)
    prepack_kernel<<<(MQ * KP2 + 255) / 256, 256>>>(hyb, hybH, hybL, MQ * KP2, 0);
    {
        dim3 g(MQ / 128, (NC + 127) / 128);
        gemm_pk_kernel<<<g, 256, SMEMB>>>(hybH, hybL, embH, embL, nullptr, out, MQ, NC, NC);
    }

    // 8. in-place log_softmax
    logsoftmax_kernel<<<MQ, 256>>>(out);
}

// round 6
// speedup vs baseline: 2.4070x; 1.0248x over previous
#include <cuda_runtime.h>
#include <cuda_bf16.h>
#include <math.h>
#include <stdint.h>

#define BB 32
#define SC 128
#define NM 16
#define DM 512
#define HH 8
#define DH 64
#define NC 39998
#define MQ (BB*NM)   /* 512 gathered query rows */
#define KP2 256      /* packed pairs per row (DM/2) */

// ---------------- scratch (device globals; no allocation allowed) -------------
__device__ float g_curr[BB*SC*DM];
__device__ float g_K[BB*SC*DM];
__device__ float g_V[BB*SC*DM];
__device__ float g_Qin[MQ*DM];
__device__ float g_Q[MQ*DM];
__device__ float g_attn[MQ*DM];
__device__ float g_hyb[MQ*DM];

// packed bf16 hi/lo operands
__device__ unsigned g_pk_embH[(size_t)NC*KP2];
__device__ unsigned g_pk_embL[(size_t)NC*KP2];
__device__ unsigned g_pk_currH[BB*SC*KP2];
__device__ unsigned g_pk_currL[BB*SC*KP2];
__device__ unsigned g_pk_wH[4*DM*KP2];   // wk, wv, wq, t2w
__device__ unsigned g_pk_wL[4*DM*KP2];
__device__ unsigned g_pk_qinH[MQ*KP2];
__device__ unsigned g_pk_qinL[MQ*KP2];
__device__ unsigned g_pk_tanhH[MQ*KP2];
__device__ unsigned g_pk_tanhL[MQ*KP2];
__device__ unsigned g_pk_hybH[MQ*KP2];
__device__ unsigned g_pk_hybL[MQ*KP2];

// ---------------- bf16 split helper ------------------------------------------
__device__ __forceinline__ void split_pack(float x, float y,
                                           unsigned& hi, unsigned& lo) {
    __nv_bfloat16 hx = __float2bfloat16_rn(x);
    __nv_bfloat16 hy = __float2bfloat16_rn(y);
    float rx = x - __bfloat162float(hx);
    float ry = y - __bfloat162float(hy);
    __nv_bfloat16 lx = __float2bfloat16_rn(rx);
    __nv_bfloat16 ly = __float2bfloat16_rn(ry);
    hi = ((unsigned)__bfloat16_as_ushort(hy) << 16) | __bfloat16_as_ushort(hx);
    lo = ((unsigned)__bfloat16_as_ushort(ly) << 16) | __bfloat16_as_ushort(lx);
}

// ---------------- kernel: gather + positional embedding ----------------------
__global__ void gather_pe_kernel(const int* __restrict__ idx,
                                 const float* __restrict__ emb,
                                 float* __restrict__ out) {
    int i = blockIdx.x * blockDim.x + threadIdx.x;
    if (i >= BB * SC * DM) return;
    int d   = i & (DM - 1);
    int row = i / DM;
    int s   = row & (SC - 1);
    int g   = idx[row];
    int i2  = d & ~1;
    float freq = expf((float)i2 * -0.0179889460176f);   // -ln(10000)/512
    float ang  = (float)s * freq;
    float pe   = (d & 1) ? cosf(ang) : sinf(ang);
    out[i] = emb[(size_t)g * DM + d] + pe;
}

// ---------------- kernel: gather Q input rows --------------------------------
__global__ void gather_q_kernel(const int* __restrict__ mask_pos,
                                const float* __restrict__ curr,
                                float* __restrict__ out) {
    int i = blockIdx.x * blockDim.x + threadIdx.x;
    if (i >= MQ * DM) return;
    int d = i & (DM - 1);
    int r = i / DM;
    int b = r / NM;
    int p = mask_pos[r];
    out[i] = curr[((size_t)b * SC + p) * DM + d];
}

// ---------------- kernel: prepack float -> packed bf16 hi/lo ------------------
__global__ void prepack_kernel(const float* __restrict__ in,
                               unsigned* __restrict__ H,
                               unsigned* __restrict__ L,
                               long npairs, int do_tanh) {
    long i = (long)blockIdx.x * blockDim.x + threadIdx.x;
    if (i >= npairs) return;
    float2 v = ((const float2*)in)[i];
    if (do_tanh) { v.x = tanhf(v.x); v.y = tanhf(v.y); }
    split_pack(v.x, v.y, H[i], L[i]);
}

// ---------------- mma / ldmatrix / cp.async helpers ----------------------------
__device__ __forceinline__ void mma_bf16(float* c, const unsigned* a, const unsigned* b) {
    asm("mma.sync.aligned.m16n8k16.row.col.f32.bf16.bf16.f32 "
        "{%0,%1,%2,%3}, {%4,%5,%6,%7}, {%8,%9}, {%0,%1,%2,%3};"
        : "+f"(c[0]), "+f"(c[1]), "+f"(c[2]), "+f"(c[3])
        : "r"(a[0]), "r"(a[1]), "r"(a[2]), "r"(a[3]), "r"(b[0]), "r"(b[1]));
}
__device__ __forceinline__ void cp16(unsigned* dst, const unsigned* src, bool ok) {
    unsigned d = (unsigned)__cvta_generic_to_shared(dst);
    int sz = ok ? 16 : 0;
    asm volatile("cp.async.cg.shared.global [%0], [%1], 16, %2;"
                 :: "r"(d), "l"(src), "r"(sz));
}
#define LDSM4(r, a)                                                          \
    asm volatile("ldmatrix.sync.aligned.m8n8.x4.shared.b16 {%0,%1,%2,%3}, [%4];" \
                 : "=r"((r)[0]), "=r"((r)[1]), "=r"((r)[2]), "=r"((r)[3])    \
                 : "r"(a))

// ---------------- prepacked tensor-core GEMM ----------------------------------
// C[M,N] = A[M,512] @ B[N,512]^T + bias, A/B prepacked bf16 hi/lo pairs.
// grid: (M/128, ceil(N/128)) — M fastest so M-blocks share B tiles via L2.
// 128x128 block tile, BK=32 (16 pairs), 8 warps 64x32, bf16x3, double-buffered
// cp.async staging, ldmatrix fragment loads.
#define PITCH 20
#define TSZ (128*PITCH)
__global__ __launch_bounds__(256)
void gemm_pk_kernel(const unsigned* __restrict__ AH, const unsigned* __restrict__ AL,
                    const unsigned* __restrict__ BH, const unsigned* __restrict__ BL,
                    const float* __restrict__ bias,
                    float* __restrict__ C,
                    int M, int N, int ldc) {
    extern __shared__ unsigned sm[];
    uint32_t smem_u32 = (uint32_t)__cvta_generic_to_shared(sm);

    int bm = blockIdx.x * 128;
    int bn = blockIdx.y * 128;
    int tid = threadIdx.x;
    int wid = tid >> 5;
    int lane = tid & 31;
    int warp_m = wid >> 2;           // 0..1
    int warp_n = wid & 3;            // 0..3
    int g  = lane >> 2;              // 0..7
    int tg = lane & 3;               // 0..3
    int m_base = warp_m * 64;
    int n_base = warp_n * 32;

    // ldmatrix address components (per lane, fixed across the loop)
    int a_row = m_base + (lane & 15);          // + mt*16
    int a_col = (lane >> 4) * 4;               // + kc
    int b_row = n_base + ((lane >> 4) & 1) * 8 + (lane & 7);  // + np*16
    int b_col = ((lane >> 3) & 1) * 4;         // + kc

    float acc[4][4][4];
#pragma unroll
    for (int mt = 0; mt < 4; ++mt)
#pragma unroll
        for (int nt = 0; nt < 4; ++nt)
#pragma unroll
            for (int i = 0; i < 4; ++i) acc[mt][nt][i] = 0.f;

    // staging: each tile is 128 rows x 16 uint32 per array; 512 uint4 per array;
    // per thread: 2 chunks x 4 arrays = 8 cp.async of 16B.
    int srow0 = tid >> 2;            // chunk 0 row
    int sc4   = (tid & 3) * 4;       // uint32 col within 16
    int srow1 = (tid + 256) >> 2;    // chunk 1 row

#define STAGE(buf, k0p)                                                          \
    {                                                                            \
        unsigned* bAH = sm + (buf) * 4 * TSZ;                                    \
        unsigned* bAL = bAH + TSZ;                                               \
        unsigned* bBH = bAH + 2 * TSZ;                                           \
        unsigned* bBL = bAH + 3 * TSZ;                                           \
        _Pragma("unroll")                                                        \
        for (int i = 0; i < 2; ++i) {                                            \
            int row = i ? srow1 : srow0;                                         \
            const unsigned* aH = AH + (size_t)(bm + row) * KP2 + (k0p) + sc4;    \
            const unsigned* aL = AL + (size_t)(bm + row) * KP2 + (k0p) + sc4;    \
            cp16(bAH + row * PITCH + sc4, aH, true);                             \
            cp16(bAL + row * PITCH + sc4, aL, true);                             \
            int nrow = bn + row;                                                 \
            bool ok = nrow < N;                                                  \
            int nrc = ok ? nrow : 0;                                             \
            const unsigned* bH = BH + (size_t)nrc * KP2 + (k0p) + sc4;           \
            const unsigned* bL = BL + (size_t)nrc * KP2 + (k0p) + sc4;           \
            cp16(bBH + row * PITCH + sc4, bH, ok);                               \
            cp16(bBL + row * PITCH + sc4, bL, ok);                               \
        }                                                                        \
    }

    STAGE(0, 0);
    asm volatile("cp.async.commit_group;");

    const int NSTEP = DM / 32;       // 16
    for (int s = 0; s < NSTEP; ++s) {
        if (s + 1 < NSTEP) {
            STAGE((s + 1) & 1, (s + 1) * 16);
            asm volatile("cp.async.commit_group;");
            asm volatile("cp.async.wait_group 1;");
        } else {
            asm volatile("cp.async.wait_group 0;");
        }
        __syncthreads();

        uint32_t baseAH = smem_u32 + ((s & 1) * 4 * TSZ) * 4;
        uint32_t baseAL = baseAH + TSZ * 4;
        uint32_t baseBH = baseAH + 2 * TSZ * 4;
        uint32_t baseBL = baseAH + 3 * TSZ * 4;

#pragma unroll
        for (int ks = 0; ks < 2; ++ks) {
            int kc = ks * 8;
            unsigned ah[4][4], al[4][4];
#pragma unroll
            for (int mt = 0; mt < 4; ++mt) {
                uint32_t off = (uint32_t)(((a_row + mt * 16) * PITCH + kc + a_col) * 4);
                LDSM4(ah[mt], baseAH + off);
                LDSM4(al[mt], baseAL + off);
            }
            unsigned bh[4][2], bl[4][2];
#pragma unroll
            for (int np = 0; np < 2; ++np) {
                uint32_t off = (uint32_t)(((b_row + np * 16) * PITCH + kc + b_col) * 4);
                unsigned rh[4], rl[4];
                LDSM4(rh, baseBH + off);
                LDSM4(rl, baseBL + off);
                bh[np * 2][0]     = rh[0]; bh[np * 2][1]     = rh[1];
                bh[np * 2 + 1][0] = rh[2]; bh[np * 2 + 1][1] = rh[3];
                bl[np * 2][0]     = rl[0]; bl[np * 2][1]     = rl[1];
                bl[np * 2 + 1][0] = rl[2]; bl[np * 2 + 1][1] = rl[3];
            }
#pragma unroll
            for (int mt = 0; mt < 4; ++mt)
#pragma unroll
                for (int nt = 0; nt < 4; ++nt) {
                    mma_bf16(acc[mt][nt], ah[mt], bh[nt]);
                    mma_bf16(acc[mt][nt], al[mt], bh[nt]);
                    mma_bf16(acc[mt][nt], ah[mt], bl[nt]);
                }
        }
        __syncthreads();
    }

    // epilogue: c0=(g,2tg) c1=(g,2tg+1) c2=(g+8,2tg) c3=(g+8,2tg+1)
#pragma unroll
    for (int mt = 0; mt < 4; ++mt) {
        int row0 = bm + m_base + mt * 16 + g;
#pragma unroll
        for (int nt = 0; nt < 4; ++nt) {
            int col0 = bn + n_base + nt * 8 + 2 * tg;
            float b0 = 0.f, b1 = 0.f;
            if (bias) {
                if (col0 < N)     b0 = bias[col0];
                if (col0 + 1 < N) b1 = bias[col0 + 1];
            }
            if (col0 < N) {
                C[(size_t)row0 * ldc + col0]       = acc[mt][nt][0] + b0;
                C[(size_t)(row0 + 8) * ldc + col0] = acc[mt][nt][2] + b0;
            }
            if (col0 + 1 < N) {
                C[(size_t)row0 * ldc + col0 + 1]       = acc[mt][nt][1] + b1;
                C[(size_t)(row0 + 8) * ldc + col0 + 1] = acc[mt][nt][3] + b1;
            }
        }
    }
}

// ---------------- attention over gathered queries -----------------------------
__global__ __launch_bounds__(256)
void attn_kernel(const float* __restrict__ Q,
                 const float* __restrict__ K,
                 const float* __restrict__ V,
                 float* __restrict__ out) {
    int blk = blockIdx.x;
    int b = blk / HH, h = blk % HH;

    __shared__ float sQ[NM][DH];
    __shared__ float sS[NM][SC];
    __shared__ float sKV[SC][DH + 1];

    int tid = threadIdx.x;

    for (int e = tid; e < NM * DH; e += 256) {
        int m = e / DH, d0 = e % DH;
        sQ[m][d0] = Q[((size_t)b * NM + m) * DM + h * DH + d0];
    }
    for (int e = tid; e < SC * DH; e += 256) {
        int k = e / DH, d0 = e % DH;
        sKV[k][d0] = K[((size_t)b * SC + k) * DM + h * DH + d0];
    }
    __syncthreads();

    for (int e = tid; e < NM * SC; e += 256) {
        int m = e / SC, k = e % SC;
        float acc = 0.f;
#pragma unroll
        for (int d0 = 0; d0 < DH; ++d0) acc += sQ[m][d0] * sKV[k][d0];
        sS[m][k] = acc;
    }
    __syncthreads();

    int w = tid >> 5, lane = tid & 31;
    for (int m = 2 * w; m < 2 * w + 2; ++m) {
        float vals[4];
        float mx = -INFINITY;
#pragma unroll
        for (int j = 0; j < 4; ++j) {
            vals[j] = sS[m][lane * 4 + j];
            mx = fmaxf(mx, vals[j]);
        }
#pragma unroll
        for (int off = 16; off; off >>= 1)
            mx = fmaxf(mx, __shfl_xor_sync(0xffffffffu, mx, off));
        float sum = 0.f;
#pragma unroll
        for (int j = 0; j < 4; ++j) {
            vals[j] = expf(vals[j] - mx);
            sum += vals[j];
        }
#pragma unroll
        for (int off = 16; off; off >>= 1)
            sum += __shfl_xor_sync(0xffffffffu, sum, off);
        float inv = 1.f / sum;
#pragma unroll
        for (int j = 0; j < 4; ++j) sS[m][lane * 4 + j] = vals[j] * inv;
    }
    __syncthreads();

    for (int e = tid; e < SC * DH; e += 256) {
        int k = e / DH, d0 = e % DH;
        sKV[k][d0] = V[((size_t)b * SC + k) * DM + h * DH + d0];
    }
    __syncthreads();

    for (int e = tid; e < NM * DH; e += 256) {
        int m = e / DH, d0 = e % DH;
        float acc = 0.f;
#pragma unroll
        for (int k = 0; k < SC; ++k) acc += sS[m][k] * sKV[k][d0];
        out[((size_t)b * NM + m) * DM + h * DH + d0] = acc;
    }
}

// ---------------- in-place row log_softmax (online max+sum) -------------------
__global__ __launch_bounds__(256)
void logsoftmax_kernel(float* __restrict__ out) {
    int row = blockIdx.x;
    float* p = out + (size_t)row * NC;
    __shared__ float rm[256], rs[256];
    int t = threadIdx.x;

    float m = -INFINITY, s = 0.f;
    for (int i = t; i < NC; i += 256) {
        float v = p[i];
        float nm = fmaxf(m, v);
        s = s * __expf(m - nm) + __expf(v - nm);
        m = nm;
    }
    rm[t] = m; rs[t] = s;
    __syncthreads();
    for (int st = 128; st; st >>= 1) {
        if (t < st) {
            float m2 = rm[t + st], s2 = rs[t + st];
            float nm = fmaxf(rm[t], m2);
            rs[t] = rs[t] * __expf(rm[t] - nm) + s2 * __expf(m2 - nm);
            rm[t] = nm;
        }
        __syncthreads();
    }
    float lse = rm[0] + logf(rs[0]);
    __syncthreads();

    for (int i = t; i < NC; i += 256) p[i] = p[i] - lse;
}

// ---------------- launch -----------------------------------------------------
extern "C" void kernel_launch(void* const* d_in, const int* in_sizes, int n_in,
                              void* d_out, int out_size) {
    const int*   mask_pos  = (const int*)d_in[2];
    const int*   mask_curr = (const int*)d_in[3];
    const float* emb       = (const float*)d_in[5];
    const float* c_wq = (const float*)d_in[12];
    const float* c_bq = (const float*)d_in[13];
    const float* c_wk = (const float*)d_in[14];
    const float* c_bk = (const float*)d_in[15];
    const float* c_wv = (const float*)d_in[16];
    const float* c_bv = (const float*)d_in[17];
    const float* t2_w = (const float*)d_in[24];
    const float* t2_b = (const float*)d_in[25];
    float* out = (float*)d_out;

    float *curr, *Kb, *Vb, *Qin, *Qb, *attn, *hyb;
    cudaGetSymbolAddress((void**)&curr, g_curr);
    cudaGetSymbolAddress((void**)&Kb,   g_K);
    cudaGetSymbolAddress((void**)&Vb,   g_V);
    cudaGetSymbolAddress((void**)&Qin,  g_Qin);
    cudaGetSymbolAddress((void**)&Qb,   g_Q);
    cudaGetSymbolAddress((void**)&attn, g_attn);
    cudaGetSymbolAddress((void**)&hyb,  g_hyb);

    unsigned *embH, *embL, *currH, *currL, *wH, *wL;
    unsigned *qinH, *qinL, *tanhH, *tanhL, *hybH, *hybL;
    cudaGetSymbolAddress((void**)&embH,  g_pk_embH);
    cudaGetSymbolAddress((void**)&embL,  g_pk_embL);
    cudaGetSymbolAddress((void**)&currH, g_pk_currH);
    cudaGetSymbolAddress((void**)&currL, g_pk_currL);
    cudaGetSymbolAddress((void**)&wH,    g_pk_wH);
    cudaGetSymbolAddress((void**)&wL,    g_pk_wL);
    cudaGetSymbolAddress((void**)&qinH,  g_pk_qinH);
    cudaGetSymbolAddress((void**)&qinL,  g_pk_qinL);
    cudaGetSymbolAddress((void**)&tanhH, g_pk_tanhH);
    cudaGetSymbolAddress((void**)&tanhL, g_pk_tanhL);
    cudaGetSymbolAddress((void**)&hybH,  g_pk_hybH);
    cudaGetSymbolAddress((void**)&hybL,  g_pk_hybL);

    cudaFuncSetAttribute(gemm_pk_kernel,
                         cudaFuncAttributeMaxDynamicSharedMemorySize, 2 * 4 * TSZ * 4);
    const int SMEMB = 2 * 4 * TSZ * 4;   // 81920 bytes

    const long WP = (long)DM * KP2;      // pairs per 512x512 matrix

    // 1. curr = emb[mask_curr] + PE
    gather_pe_kernel<<<(BB * SC * DM + 255) / 256, 256>>>(mask_curr, emb, curr);

    // 2. prepack operands
    prepack_kernel<<<(int)((WP + 255) / 256), 256>>>(c_wk, wH,          wL,          WP, 0);
    prepack_kernel<<<(int)((WP + 255) / 256), 256>>>(c_wv, wH + WP,     wL + WP,     WP, 0);
    prepack_kernel<<<(int)((WP + 255) / 256), 256>>>(c_wq, wH + 2 * WP, wL + 2 * WP, WP, 0);
    prepack_kernel<<<(int)((WP + 255) / 256), 256>>>(t2_w, wH + 3 * WP, wL + 3 * WP, WP, 0);
    {
        long np = (long)NC * KP2;
        prepack_kernel<<<(int)((np + 255) / 256), 256>>>(emb + 2 * DM, embH, embL, np, 0);
    }
    {
        long np = (long)BB * SC * KP2;
        prepack_kernel<<<(int)((np + 255) / 256), 256>>>(curr, currH, currL, np, 0);
    }

    // 3. K, V projections over all 4096 rows
    {
        dim3 g((BB * SC) / 128, DM / 128);
        gemm_pk_kernel<<<g, 256, SMEMB>>>(currH, currL, wH,      wL,      c_bk, Kb, BB * SC, DM, DM);
        gemm_pk_kernel<<<g, 256, SMEMB>>>(currH, currL, wH + WP, wL + WP, c_bv, Vb, BB * SC, DM, DM);
    }

    // 4. Q projection over the 512 gathered rows
    gather_q_kernel<<<(MQ * DM + 255) / 256, 256>>>(mask_pos, curr, Qin);
    prepack_kernel<<<(MQ * KP2 + 255) / 256, 256>>>(Qin, qinH, qinL, MQ * KP2, 0);
    {
        dim3 g(MQ / 128, DM / 128);
        gemm_pk_kernel<<<g, 256, SMEMB>>>(qinH, qinL, wH + 2 * WP, wL + 2 * WP, c_bq, Qb, MQ, DM, DM);
    }

    // 5. attention
    attn_kernel<<<BB * HH, 256>>>(Qb, Kb, Vb, attn);

    // 6. hyb = tanh(attn) @ t2_w^T + t2_b  (tanh fused into prepack)
    prepack_kernel<<<(MQ * KP2 + 255) / 256, 256>>>(attn, tanhH, tanhL, MQ * KP2, 1);
    {
        dim3 g(MQ / 128, DM / 128);
        gemm_pk_kernel<<<g, 256, SMEMB>>>(tanhH, tanhL, wH + 3 * WP, wL + 3 * WP, t2_b, hyb, MQ, DM, DM);
    }

    // 7. scores = hyb @ emb[2:]^T  (into d_out)
    prepack_kernel<<<(MQ * KP2 + 255) / 256, 256>>>(hyb, hybH, hybL, MQ * KP2, 0);
    {
        dim3 g(MQ / 128, (NC + 127) / 128);
        gemm_pk_kernel<<<g, 256, SMEMB>>>(hybH, hybL, embH, embL, nullptr, out, MQ, NC, NC);
    }

    // 8. in-place log_softmax
    logsoftmax_kernel<<<MQ, 256>>>(out);
}